// round 17
// baseline (speedup 1.0000x reference)
#include <cuda_runtime.h>
#include <cstdint>

// out[i, b*O + o] = input[b, i] * exp(weight[i, o]) + bias[i, o]
// I = 512, O = 128, B = 2048. Output fp32, 512 MB -> HBM-write-roofline.
//
// R16: persistent-CTA variant of the R8 winner (74.0us, DRAM~80%).
// Same per-tile structure (32KB SMEM stage -> one cp.async.bulk SMEM->GMEM,
// L1-bypass, L2::evict_first), but a fixed grid of 152*7=1064 CTAs
// grid-strides over all 16384 tiles, reusing its SMEM buffer. Removes ~15
// wave transitions + 15k CTA launch/drain ramps; probes whether the
// ~20% DRAM headroom contains any scheduling overhead or is pure HBM
// write-stream physics (run-to-run noise established at +-1us in R15).

#define I_FEATS   512
#define O_FEATS   128
#define BATCH     2048
#define B_PER_CTA 64                         // batches per tile
#define NCHUNK    (BATCH / B_PER_CTA)        // 32
#define NTILES    (NCHUNK * I_FEATS)         // 16384
#define ITERS     (B_PER_CTA / 8)            // 8 warps -> 8 batches each
#define TILE_ELEMS (B_PER_CTA * O_FEATS)     // 8192 floats
#define TILE_BYTES (TILE_ELEMS * 4)          // 32 KB
#define NCTAS     (152 * 7)                  // 1064 persistent CTAs

__global__ void __launch_bounds__(256)
linear_nosum_tma_pers_kernel(const float* __restrict__ input,
                             const float* __restrict__ weight,
                             const float* __restrict__ bias,
                             float* __restrict__ out)
{
    __shared__ alignas(128) float buf[TILE_ELEMS];   // 32 KB static

    const int warp = threadIdx.x >> 5;       // 0..7
    const int lane = threadIdx.x & 31;       // 0..31
    const int o    = lane << 2;              // output column base

    uint64_t pol;
    asm("createpolicy.fractional.L2::evict_first.b64 %0, 1.0;" : "=l"(pol));

    for (int t = blockIdx.x; t < NTILES; t += NCTAS) {
        const int i     = t >> 5;            // feature row 0..511
        const int chunk = t & 31;            // batch chunk 0..31

        // Per-tile constants (weight/bias are L2-resident; exp recompute is
        // ~4 MUFU warp-instr per warp per tile — negligible, see R16 notes).
        const float4 w4 = *reinterpret_cast<const float4*>(weight + i * O_FEATS + o);
        const float4 b4 = *reinterpret_cast<const float4*>(bias   + i * O_FEATS + o);
        const float e0 = expf(w4.x);
        const float e1 = expf(w4.y);
        const float e2 = expf(w4.z);
        const float e3 = expf(w4.w);

        const int b0 = chunk * B_PER_CTA + warp;
        const float* __restrict__ in_ptr = input + (size_t)b0 * I_FEATS + i;

        // Front-batch the 8 strided input scalars (MLP=8).
        float xs[ITERS];
#pragma unroll
        for (int k = 0; k < ITERS; k++)
            xs[k] = __ldg(in_ptr + (size_t)(k << 3) * I_FEATS);

        // Fill the SMEM tile (STS.128, conflict-free).
#pragma unroll
        for (int k = 0; k < ITERS; k++) {
            const float x = xs[k];
            float4 r;
            r.x = fmaf(x, e0, b4.x);
            r.y = fmaf(x, e1, b4.y);
            r.z = fmaf(x, e2, b4.z);
            r.w = fmaf(x, e3, b4.w);
            *reinterpret_cast<float4*>(buf + (warp + (k << 3)) * O_FEATS + o) = r;
        }
        __syncthreads();

        // One 32KB bulk TMA store of the contiguous tile (L1-bypass).
        if (threadIdx.x == 0) {
            uint32_t saddr;
            asm("{ .reg .u64 tt; cvta.to.shared.u64 tt, %1; cvt.u32.u64 %0, tt; }"
                : "=r"(saddr) : "l"(buf));
            float* g = out + (size_t)i * ((size_t)BATCH * O_FEATS)
                           + (size_t)chunk * TILE_ELEMS;
            // Order generic-proxy STS before the async-proxy bulk read.
            asm volatile("fence.proxy.async.shared::cta;" ::: "memory");
            asm volatile(
                "cp.async.bulk.global.shared::cta.bulk_group.L2::cache_hint "
                "[%0], [%1], %2, %3;"
                :: "l"(g), "r"(saddr), "r"((uint32_t)TILE_BYTES), "l"(pol)
                : "memory");
            asm volatile("cp.async.bulk.commit_group;" ::: "memory");
            // Buffer is reused next iteration: the bulk read must finish.
            asm volatile("cp.async.bulk.wait_group.read 0;" ::: "memory");
        }
        // All threads see the buffer as free before refilling it.
        __syncthreads();
    }
}

extern "C" void kernel_launch(void* const* d_in, const int* in_sizes, int n_in,
                              void* d_out, int out_size)
{
    const float* input  = (const float*)d_in[0];
    const float* weight = (const float*)d_in[1];
    const float* bias   = (const float*)d_in[2];
    float* out = (float*)d_out;

    linear_nosum_tma_pers_kernel<<<NCTAS, 256>>>(input, weight, bias, out);
}